// round 3
// baseline (speedup 1.0000x reference)
#include <cuda_runtime.h>
#include <cuda_bf16.h>
#include <cstdint>
#include <cstddef>

// Problem constants (fixed by setup_inputs)
#define BATCH 2
#define LSEQ  2048
#define DIM   512
#define NHEAD 8
#define HDIM  64
#define EPSV  1e-8f
#define NBH   (BATCH * NHEAD)

// Pre-split bf16 scratch rows: [bh][i][ hi d=0..63 | lo d=0..63 ]
__device__ __nv_bfloat16 g_Xp[(size_t)NBH * LSEQ * 128];
__device__ __nv_bfloat16 g_Yp[(size_t)NBH * LSEQ * 128];

// ---------------------------------------------------------------------------
// Kernel 1: sequential cumprod scan per (b, channel); emits bf16 hi/lo of
// X = C*P and Y = B/D. 1024 independent chains.
// ---------------------------------------------------------------------------
static __device__ __forceinline__ void put_split(__nv_bfloat16* base, size_t off,
                                                 float v) {
    __nv_bfloat16 h = __float2bfloat16(v);            // RN
    float lo = v - __bfloat162float(h);
    base[off]      = h;
    base[off + 64] = __float2bfloat16(lo);
}

__global__ void precompute_kernel(const float* __restrict__ Bp,
                                  const float* __restrict__ Cp,
                                  const float* __restrict__ Sp) {
    int tid = blockIdx.x * blockDim.x + threadIdx.x;   // 0..1023
    if (tid >= BATCH * DIM) return;
    int b  = tid >> 9;
    int c  = tid & (DIM - 1);
    int h  = c >> 6;
    int dd = c & (HDIM - 1);

    size_t inBase  = (size_t)b * LSEQ * DIM + c;
    size_t outBase = ((size_t)(b * NHEAD + h) * LSEQ) * 128 + dd;

    float q = 1.0f;
    put_split(g_Xp, outBase, Cp[inBase]);
    put_split(g_Yp, outBase, Bp[inBase]);
    #pragma unroll 4
    for (int i = 1; i < LSEQ; ++i) {
        float a  = Sp[inBase + (size_t)i * DIM];
        float bv = Bp[inBase + (size_t)i * DIM];
        float cv = Cp[inBase + (size_t)i * DIM];
        put_split(g_Xp, outBase + (size_t)i * 128, cv * q);
        put_split(g_Yp, outBase + (size_t)i * 128, bv / (q + EPSV));
        q *= a;
    }
}

// ---------------------------------------------------------------------------
// mma.sync helpers (plain PTX, valid on target sm_103)
// ---------------------------------------------------------------------------
static __device__ __forceinline__ uint32_t smem_u32(const void* p) {
    uint32_t a;
    asm("{ .reg .u64 t; cvta.to.shared.u64 t, %1; cvt.u32.u64 %0, t; }"
        : "=r"(a) : "l"(p));
    return a;
}

#define LDSM_X4(r0, r1, r2, r3, addr) \
    asm volatile("ldmatrix.sync.aligned.m8n8.x4.shared.b16 {%0,%1,%2,%3}, [%4];" \
                 : "=r"(r0), "=r"(r1), "=r"(r2), "=r"(r3) : "r"(addr))

#define MMA_BF16(d, a, b) \
    asm volatile("mma.sync.aligned.m16n8k16.row.col.f32.bf16.bf16.f32 " \
                 "{%0,%1,%2,%3}, {%4,%5,%6,%7}, {%8,%9}, {%0,%1,%2,%3};" \
                 : "+f"((d)[0]), "+f"((d)[1]), "+f"((d)[2]), "+f"((d)[3]) \
                 : "r"((a)[0]), "r"((a)[1]), "r"((a)[2]), "r"((a)[3]), \
                   "r"((b)[0]), "r"((b)[1]))

#define CP_ASYNC16(dst, src) \
    asm volatile("cp.async.cg.shared.global [%0], [%1], 16;" \
                 :: "r"(dst), "l"(src) : "memory")

// ---------------------------------------------------------------------------
// Kernel 2: triangular batched GEMM T = X @ Y^T via bf16 3-term mma.sync.
// 128x128 tile, 256 threads (8 warps in 2x4), warp tile 64x32.
// SMEM rows: 128 bf16 = 256B = 16 chunks of 16B; chunk swizzle c ^ (row & 7).
// ---------------------------------------------------------------------------
#define SM_A 0
#define SM_B 32768
#define SM_TOTAL 65536

__global__ __launch_bounds__(256, 2)
void mma_gemm_kernel(float* __restrict__ out) {
    const int bh = blockIdx.z;
    const int ti = blockIdx.y;
    const int tj = blockIdx.x;
    const int tid = threadIdx.x;
    const int iBase = ti * 128;
    const int jBase = tj * 128;
    float* outM = out + (size_t)bh * LSEQ * LSEQ;

    if (tj > ti) {
        // strictly-upper tile: zero fill only
        float4 z = make_float4(0.f, 0.f, 0.f, 0.f);
        int row = tid >> 1;
        float4* p = (float4*)(outM + (size_t)(iBase + row) * LSEQ + jBase
                              + (tid & 1) * 64);
        #pragma unroll
        for (int c = 0; c < 16; ++c) p[c] = z;
        return;
    }

    extern __shared__ char smem[];
    const uint32_t smem_base = smem_u32(smem);

    // ---- async copy X/Y bf16 tiles into swizzled smem ----
    const __nv_bfloat16* Xb = g_Xp + (size_t)bh * LSEQ * 128;
    const __nv_bfloat16* Yb = g_Yp + (size_t)bh * LSEQ * 128;
    #pragma unroll
    for (int t = 0; t < 8; ++t) {
        int idx = t * 256 + tid;        // 0..2047
        int row = idx >> 4;             // 0..127
        int c   = idx & 15;             // 16B chunk in row
        uint32_t soff = (uint32_t)(row * 256 + ((c ^ (row & 7)) * 16));
        CP_ASYNC16(smem_base + SM_A + soff,
                   Xb + (size_t)(iBase + row) * 128 + c * 8);
        CP_ASYNC16(smem_base + SM_B + soff,
                   Yb + (size_t)(jBase + row) * 128 + c * 8);
    }
    asm volatile("cp.async.commit_group;" ::: "memory");
    asm volatile("cp.async.wait_group 0;" ::: "memory");
    __syncthreads();

    const int w    = tid >> 5;
    const int lane = tid & 31;
    const int wm = w >> 2;              // 0..1  (rows wm*64)
    const int wn = w & 3;               // 0..3  (cols wn*32)
    const int lr = lane & 15;           // ldmatrix row select
    const int lc = lane >> 4;           // ldmatrix k-chunk select
    const int swz = lr & 7;

    float acc[4][4][4];
    #pragma unroll
    for (int mt = 0; mt < 4; ++mt)
        #pragma unroll
        for (int nt = 0; nt < 4; ++nt)
            #pragma unroll
            for (int e = 0; e < 4; ++e) acc[mt][nt][e] = 0.f;

    const uint32_t aRowBase = smem_base + SM_A + (uint32_t)((wm * 64 + lr) * 256);
    const uint32_t bRowBase = smem_base + SM_B + (uint32_t)((wn * 32 + lr) * 256);

    // 3 passes: (Ahi,Bhi), (Ahi,Blo), (Alo,Bhi). hi = chunks 0..7, lo = 8..15.
    #pragma unroll
    for (int p = 0; p < 3; ++p) {
        const int acBase = (p == 2) ? 8 : 0;
        const int bcBase = (p == 1) ? 8 : 0;
        #pragma unroll
        for (int ks = 0; ks < 4; ++ks) {
            uint32_t a[4][4];
            #pragma unroll
            for (int mt = 0; mt < 4; ++mt) {
                uint32_t addr = aRowBase + (uint32_t)(mt * 16 * 256)
                              + (uint32_t)(((acBase + 2 * ks + lc) ^ swz) * 16);
                LDSM_X4(a[mt][0], a[mt][1], a[mt][2], a[mt][3], addr);
            }
            uint32_t bf[4][2];
            #pragma unroll
            for (int nh = 0; nh < 2; ++nh) {
                uint32_t m0, m1, m2, m3;
                uint32_t addr = bRowBase + (uint32_t)(nh * 16 * 256)
                              + (uint32_t)(((bcBase + 2 * ks + lc) ^ swz) * 16);
                LDSM_X4(m0, m1, m2, m3, addr);
                bf[nh * 2][0] = m0; bf[nh * 2][1] = m2;
                bf[nh * 2 + 1][0] = m1; bf[nh * 2 + 1][1] = m3;
            }
            #pragma unroll
            for (int mt = 0; mt < 4; ++mt)
                #pragma unroll
                for (int nt = 0; nt < 4; ++nt)
                    MMA_BF16(acc[mt][nt], a[mt], bf[nt]);
        }
    }

    // ---- epilogue: registers -> global, strict-lower mask on diag tiles ----
    const bool diagTile = (ti == tj);
    const int r  = lane >> 2;
    const int cb = (lane & 3) * 2;
    #pragma unroll
    for (int mt = 0; mt < 4; ++mt) {
        const int gr0 = iBase + wm * 64 + mt * 16 + r;
        #pragma unroll
        for (int nt = 0; nt < 4; ++nt) {
            const int gc = jBase + wn * 32 + nt * 8 + cb;
            float2 v0, v1;
            v0.x = acc[mt][nt][0]; v0.y = acc[mt][nt][1];   // row gr0
            v1.x = acc[mt][nt][2]; v1.y = acc[mt][nt][3];   // row gr0 + 8
            if (diagTile) {
                if (gc     >= gr0)     v0.x = 0.f;
                if (gc + 1 >= gr0)     v0.y = 0.f;
                if (gc     >= gr0 + 8) v1.x = 0.f;
                if (gc + 1 >= gr0 + 8) v1.y = 0.f;
            }
            *(float2*)(outM + (size_t)gr0 * LSEQ + gc)       = v0;
            *(float2*)(outM + (size_t)(gr0 + 8) * LSEQ + gc) = v1;
        }
    }
}

// ---------------------------------------------------------------------------
// Kernel 3: diagonal T_ii = C_i . B_i  (one warp per (b,h,i))
// ---------------------------------------------------------------------------
__global__ void diag_kernel(const float* __restrict__ Bp,
                            const float* __restrict__ Cp,
                            float* __restrict__ out) {
    int warpId = (blockIdx.x * blockDim.x + threadIdx.x) >> 5;
    int lane = threadIdx.x & 31;
    if (warpId >= BATCH * NHEAD * LSEQ) return;
    int b   = warpId >> 14;
    int rem = warpId & (NHEAD * LSEQ - 1);
    int h   = rem >> 11;
    int i   = rem & (LSEQ - 1);
    size_t base = ((size_t)b * LSEQ + i) * DIM + h * HDIM + lane;
    float s = Cp[base] * Bp[base] + Cp[base + 32] * Bp[base + 32];
    #pragma unroll
    for (int off = 16; off; off >>= 1)
        s += __shfl_down_sync(0xffffffffu, s, off);
    if (lane == 0)
        out[(((size_t)(b * NHEAD + h) * LSEQ) + i) * LSEQ + i] = s;
}

// ---------------------------------------------------------------------------
extern "C" void kernel_launch(void* const* d_in, const int* in_sizes, int n_in,
                              void* d_out, int out_size) {
    (void)in_sizes; (void)n_in; (void)out_size;
    const float* B = (const float*)d_in[0];
    const float* C = (const float*)d_in[1];
    const float* S = (const float*)d_in[2];
    float* out = (float*)d_out;

    precompute_kernel<<<8, 128>>>(B, C, S);

    cudaFuncSetAttribute(mma_gemm_kernel,
                         cudaFuncAttributeMaxDynamicSharedMemorySize, SM_TOTAL);
    dim3 grid(LSEQ / 128, LSEQ / 128, BATCH * NHEAD);
    mma_gemm_kernel<<<grid, 256, SM_TOTAL>>>(out);

    int nWarps = BATCH * NHEAD * LSEQ;
    diag_kernel<<<(nWarps * 32) / 256, 256>>>(B, C, out);
}